// round 5
// baseline (speedup 1.0000x reference)
#include <cuda_runtime.h>
#include <cstdint>

#define NHEADS   16
#define M_TBL    524288
#define D_IN     32
#define HID      64
#define NOUT     3
#define TILE     128
#define THREADS  512
#define NTILES   16384
#define GRID     296            // persistent: 2 CTAs per SM
#define STRIDE   132            // padded row stride (floats)

// ---- smem layout (float offsets) ----
#define O_A0   0
#define O_A1   (O_A0 + D_IN * STRIDE)        // 4224
#define O_B    (O_A1 + D_IN * STRIDE)        // 8448
#define O_W1   (O_B  + HID * STRIDE)         // 16896
#define O_W2   (O_W1 + D_IN * HID)           // 18944
#define O_W3   (O_W2 + HID * HID)            // 23040
#define O_W4   (O_W3 + HID * HID)            // 27136
#define O_BB   (O_W4 + HID * NOUT)           // 27328: b1|b2|b3|b4
#define SMEM_FLOATS (O_BB + 200)             // 27528
#define SMEM_BYTES  (SMEM_FLOATS * 4)        // 110112

#define FMA2(acc, a, w) \
    asm("fma.rn.f32x2 %0, %1, %2, %0;" : "+l"(acc) : "l"(a), "l"(w))
#define PACK2(d, s) \
    asm("mov.b64 %0, {%1, %1};" : "=l"(d) : "f"(s))
#define UNPACK2(lo, hi, s) \
    asm("mov.b64 {%0, %1}, %2;" : "=f"(lo), "=f"(hi) : "l"(s))

// Accumulate one layer: A[K][STRIDE] x W[K][64] for this thread's 4j x 4p block.
template<int K>
__device__ __forceinline__ void layer_acc(const float* __restrict__ A,
                                          const float* __restrict__ W,
                                          const float* __restrict__ bias,
                                          int j0, int p0,
                                          unsigned long long acc[8])
{
    #pragma unroll
    for (int jj = 0; jj < 4; jj++) {
        unsigned long long b;
        PACK2(b, bias[j0 + jj]);
        acc[jj * 2 + 0] = b;
        acc[jj * 2 + 1] = b;
    }
    #pragma unroll 4
    for (int k = 0; k < K; k++) {
        const ulonglong2 a =
            *reinterpret_cast<const ulonglong2*>(&A[k * STRIDE + p0]);
        const float4 w = *reinterpret_cast<const float4*>(&W[k * HID + j0]);
        unsigned long long w0, w1, w2, w3;
        PACK2(w0, w.x); PACK2(w1, w.y); PACK2(w2, w.z); PACK2(w3, w.w);
        FMA2(acc[0], a.x, w0); FMA2(acc[1], a.y, w0);
        FMA2(acc[2], a.x, w1); FMA2(acc[3], a.y, w1);
        FMA2(acc[4], a.x, w2); FMA2(acc[5], a.y, w2);
        FMA2(acc[6], a.x, w3); FMA2(acc[7], a.y, w3);
    }
}

// relu + store the 4j x 4p block into Bout
__device__ __forceinline__ void layer_store(float* __restrict__ Bout,
                                            int j0, int p0,
                                            const unsigned long long acc[8])
{
    #pragma unroll
    for (int jj = 0; jj < 4; jj++) {
        float v0, v1, v2, v3;
        UNPACK2(v0, v1, acc[jj * 2 + 0]);
        UNPACK2(v2, v3, acc[jj * 2 + 1]);
        *reinterpret_cast<float4*>(&Bout[(j0 + jj) * STRIDE + p0]) =
            make_float4(fmaxf(v0, 0.f), fmaxf(v1, 0.f),
                        fmaxf(v2, 0.f), fmaxf(v3, 0.f));
    }
}

__global__ __launch_bounds__(THREADS, 2)
void ngp_persist_kernel(const int* __restrict__ idx,
                        const float* __restrict__ tables,
                        const float* __restrict__ gW1, const float* __restrict__ gb1,
                        const float* __restrict__ gW2, const float* __restrict__ gb2,
                        const float* __restrict__ gW3, const float* __restrict__ gb3,
                        const float* __restrict__ gW4, const float* __restrict__ gb4,
                        float* __restrict__ out)
{
    extern __shared__ float sm[];
    float* Abuf[2] = { sm + O_A0, sm + O_A1 };
    float* B  = sm + O_B;
    float* W1 = sm + O_W1;
    float* W2 = sm + O_W2;
    float* W3 = sm + O_W3;
    float* W4 = sm + O_W4;
    float* bb = sm + O_BB;      // [0:64) b1 [64:128) b2 [128:192) b3 [192:195) b4

    const int tid = threadIdx.x;

    // ---- one-time weight staging (amortized over ~55 tiles) ----
    for (int i = tid; i < D_IN * HID; i += THREADS) W1[i] = gW1[i];
    for (int i = tid; i < HID * HID;  i += THREADS) W2[i] = gW2[i];
    for (int i = tid; i < HID * HID;  i += THREADS) W3[i] = gW3[i];
    if (tid < HID * NOUT) W4[tid] = gW4[tid];
    if (tid < HID) { bb[tid] = gb1[tid]; bb[64+tid] = gb2[tid]; bb[128+tid] = gb3[tid]; }
    if (tid < NOUT) bb[192 + tid] = gb4[tid];

    const int j0 = (tid & 15) * 4;       // output-j block
    const int p0 = (tid >> 4) * 4;       // point block
    const int gp = tid >> 2;             // gather: point
    const int gh = (tid & 3) * 4;        // gather: head start

    // ---- gather first tile into A[0] ----
    {
        const long pbase = (long)blockIdx.x * TILE;
        const int4 iv = *reinterpret_cast<const int4*>(
            idx + (pbase + gp) * NHEADS + gh);
        const int ii[4] = { iv.x, iv.y, iv.z, iv.w };
        float* A = Abuf[0];
        #pragma unroll
        for (int i = 0; i < 4; i++) {
            const float2 v = *reinterpret_cast<const float2*>(
                tables + ((long)(gh + i) * M_TBL + ii[i]) * 2);
            A[(2 * (gh + i)    ) * STRIDE + gp] = v.x;
            A[(2 * (gh + i) + 1) * STRIDE + gp] = v.y;
        }
    }
    __syncthreads();

    int buf = 0;
    for (long t = blockIdx.x; t < NTILES; t += GRID, buf ^= 1) {
        const long pbase = (long)t * TILE;
        const bool hasNext = (t + GRID) < NTILES;

        // -- issue idx load for NEXT tile early (latency hidden by layer 1) --
        int4 nidx = make_int4(0, 0, 0, 0);
        if (hasNext)
            nidx = *reinterpret_cast<const int4*>(
                idx + ((t + GRID) * TILE + gp) * NHEADS + gh);

        unsigned long long acc[8];

        // ---- layer 1: A[buf](32) -> B ----
        layer_acc<D_IN>(Abuf[buf], W1, bb, j0, p0, acc);
        layer_store(B, j0, p0, acc);
        __syncthreads();

        // -- issue table gathers for NEXT tile (hidden by layers 2/3) --
        float2 nv[4];
        if (hasNext) {
            #pragma unroll
            for (int i = 0; i < 4; i++)
                nv[i] = *reinterpret_cast<const float2*>(
                    tables + ((long)(gh + i) * M_TBL +
                              ((const int*)&nidx)[i]) * 2);
        }

        // ---- layer 2: B(64) -> B (in place: acc, sync, store) ----
        layer_acc<HID>(B, W2, bb + 64, j0, p0, acc);
        __syncthreads();
        layer_store(B, j0, p0, acc);
        __syncthreads();

        // ---- layer 3: B(64) -> B ----
        layer_acc<HID>(B, W3, bb + 128, j0, p0, acc);
        __syncthreads();
        layer_store(B, j0, p0, acc);
        __syncthreads();

        // ---- park next tile's gather into the other A buffer ----
        if (hasNext) {
            float* A = Abuf[buf ^ 1];
            #pragma unroll
            for (int i = 0; i < 4; i++) {
                A[(2 * (gh + i)    ) * STRIDE + gp] = nv[i].x;
                A[(2 * (gh + i) + 1) * STRIDE + gp] = nv[i].y;
            }
        }

        // ---- layer 4: 64 -> 3, one thread per point ----
        if (tid < TILE) {
            float o0 = bb[192], o1 = bb[193], o2 = bb[194];
            #pragma unroll 8
            for (int k = 0; k < HID; k++) {
                const float a = B[k * STRIDE + tid];
                o0 = fmaf(a, W4[k * NOUT + 0], o0);
                o1 = fmaf(a, W4[k * NOUT + 1], o1);
                o2 = fmaf(a, W4[k * NOUT + 2], o2);
            }
            float* op = out + (pbase + tid) * NOUT;
            op[0] = o0; op[1] = o1; op[2] = o2;
        }
        __syncthreads();
    }
}

extern "C" void kernel_launch(void* const* d_in, const int* in_sizes, int n_in,
                              void* d_out, int out_size)
{
    static int init = 0;
    if (!init) {
        cudaFuncSetAttribute(ngp_persist_kernel,
                             cudaFuncAttributeMaxDynamicSharedMemorySize,
                             SMEM_BYTES);
        init = 1;
    }
    ngp_persist_kernel<<<GRID, THREADS, SMEM_BYTES>>>(
        (const int*)d_in[0], (const float*)d_in[1],
        (const float*)d_in[2], (const float*)d_in[3],
        (const float*)d_in[4], (const float*)d_in[5],
        (const float*)d_in[6], (const float*)d_in[7],
        (const float*)d_in[8], (const float*)d_in[9],
        (float*)d_out);
}

// round 6
// speedup vs baseline: 1.0086x; 1.0086x over previous
#include <cuda_runtime.h>
#include <cstdint>

#define NHEADS   16
#define M_TBL    524288
#define D_IN     32
#define HID      64
#define NOUT     3
#define TILE     128
#define THREADS  256
#define NTILES   16384
#define GRID     444            // persistent: 3 CTAs per SM
#define STRIDE   132            // padded row stride (floats)

// ---- smem layout (float offsets) ----
// Single activation buffer: 64 rows x STRIDE. Rows 0..31 double as the
// gather/A buffer (in-place acc->sync->store per layer).
#define O_BUF  0
#define O_W1   (O_BUF + HID * STRIDE)        // 8448
#define O_W2   (O_W1 + D_IN * HID)           // 10496
#define O_W3   (O_W2 + HID * HID)            // 14592
#define O_W4   (O_W3 + HID * HID)            // 18688
#define O_BB   (O_W4 + HID * NOUT)           // 18880
#define SMEM_FLOATS (O_BB + 200)             // 19080
#define SMEM_BYTES  (SMEM_FLOATS * 4)        // 76320 -> 3 CTAs/SM

#define FMA2(acc, a, w) \
    asm("fma.rn.f32x2 %0, %1, %2, %0;" : "+l"(acc) : "l"(a), "l"(w))
#define PACK2(d, s) \
    asm("mov.b64 %0, {%1, %1};" : "=l"(d) : "f"(s))
#define UNPACK2(lo, hi, s) \
    asm("mov.b64 {%0, %1}, %2;" : "=f"(lo), "=f"(hi) : "l"(s))

// Accumulate: A[K rows][STRIDE] x W[K][64] -> 4j x 8p block in acc[16].
template<int K>
__device__ __forceinline__ void layer_acc(const float* __restrict__ A,
                                          const float* __restrict__ W,
                                          const float* __restrict__ bias,
                                          int j0, int p0,
                                          unsigned long long acc[16])
{
    #pragma unroll
    for (int jj = 0; jj < 4; jj++) {
        unsigned long long b;
        PACK2(b, bias[j0 + jj]);
        #pragma unroll
        for (int pp = 0; pp < 4; pp++) acc[jj * 4 + pp] = b;
    }
    #pragma unroll 4
    for (int k = 0; k < K; k++) {
        const ulonglong2 a01 =
            *reinterpret_cast<const ulonglong2*>(&A[k * STRIDE + p0]);
        const ulonglong2 a23 =
            *reinterpret_cast<const ulonglong2*>(&A[k * STRIDE + p0 + 4]);
        const float4 w = *reinterpret_cast<const float4*>(&W[k * HID + j0]);
        unsigned long long w0, w1, w2, w3;
        PACK2(w0, w.x); PACK2(w1, w.y); PACK2(w2, w.z); PACK2(w3, w.w);
        FMA2(acc[ 0], a01.x, w0); FMA2(acc[ 1], a01.y, w0);
        FMA2(acc[ 2], a23.x, w0); FMA2(acc[ 3], a23.y, w0);
        FMA2(acc[ 4], a01.x, w1); FMA2(acc[ 5], a01.y, w1);
        FMA2(acc[ 6], a23.x, w1); FMA2(acc[ 7], a23.y, w1);
        FMA2(acc[ 8], a01.x, w2); FMA2(acc[ 9], a01.y, w2);
        FMA2(acc[10], a23.x, w2); FMA2(acc[11], a23.y, w2);
        FMA2(acc[12], a01.x, w3); FMA2(acc[13], a01.y, w3);
        FMA2(acc[14], a23.x, w3); FMA2(acc[15], a23.y, w3);
    }
}

__device__ __forceinline__ void layer_store(float* __restrict__ Bout,
                                            int j0, int p0,
                                            const unsigned long long acc[16])
{
    #pragma unroll
    for (int jj = 0; jj < 4; jj++) {
        float v[8];
        #pragma unroll
        for (int pp = 0; pp < 4; pp++)
            UNPACK2(v[2 * pp], v[2 * pp + 1], acc[jj * 4 + pp]);
        #pragma unroll
        for (int q = 0; q < 8; q++) v[q] = fmaxf(v[q], 0.0f);
        float* dst = &Bout[(j0 + jj) * STRIDE + p0];
        *reinterpret_cast<float4*>(dst)     = make_float4(v[0], v[1], v[2], v[3]);
        *reinterpret_cast<float4*>(dst + 4) = make_float4(v[4], v[5], v[6], v[7]);
    }
}

__global__ __launch_bounds__(THREADS, 3)
void ngp_persist3_kernel(const int* __restrict__ idx,
                         const float* __restrict__ tables,
                         const float* __restrict__ gW1, const float* __restrict__ gb1,
                         const float* __restrict__ gW2, const float* __restrict__ gb2,
                         const float* __restrict__ gW3, const float* __restrict__ gb3,
                         const float* __restrict__ gW4, const float* __restrict__ gb4,
                         float* __restrict__ out)
{
    extern __shared__ float sm[];
    float* BUF = sm + O_BUF;
    float* W1  = sm + O_W1;
    float* W2  = sm + O_W2;
    float* W3  = sm + O_W3;
    float* W4  = sm + O_W4;
    float* bb  = sm + O_BB;     // b1 | b2 | b3 | b4

    const int tid = threadIdx.x;

    // ---- one-time weight staging ----
    for (int i = tid; i < D_IN * HID; i += THREADS) W1[i] = gW1[i];
    for (int i = tid; i < HID * HID;  i += THREADS) W2[i] = gW2[i];
    for (int i = tid; i < HID * HID;  i += THREADS) W3[i] = gW3[i];
    if (tid < HID * NOUT) W4[tid] = gW4[tid];
    if (tid < HID) { bb[tid] = gb1[tid]; bb[64+tid] = gb2[tid]; bb[128+tid] = gb3[tid]; }
    if (tid < NOUT) bb[192 + tid] = gb4[tid];

    const int j0 = (tid & 15) * 4;       // output block (16 j-tiles of 4)
    const int p0 = (tid >> 4) * 8;       // point block  (16 p-tiles of 8)
    const int gp = tid >> 1;             // gather: point (2 threads/point)
    const int gh = (tid & 1) * 8;        // gather: head start (8 heads each)

    // ---- gather first tile into rows 0..31 ----
    {
        const int* ip = idx + ((long)blockIdx.x * TILE + gp) * NHEADS + gh;
        const int4 i0 = *reinterpret_cast<const int4*>(ip);
        const int4 i1 = *reinterpret_cast<const int4*>(ip + 4);
        const int ii[8] = { i0.x, i0.y, i0.z, i0.w, i1.x, i1.y, i1.z, i1.w };
        #pragma unroll
        for (int i = 0; i < 8; i++) {
            const float2 v = *reinterpret_cast<const float2*>(
                tables + ((long)(gh + i) * M_TBL + ii[i]) * 2);
            BUF[(2 * (gh + i)    ) * STRIDE + gp] = v.x;
            BUF[(2 * (gh + i) + 1) * STRIDE + gp] = v.y;
        }
    }
    __syncthreads();

    for (long t = blockIdx.x; t < NTILES; t += GRID) {
        const long pbase = (long)t * TILE;
        const bool hasNext = (t + GRID) < NTILES;

        // -- idx LDG for NEXT tile (latency hidden under layer 1) --
        int4 ni0 = make_int4(0,0,0,0), ni1 = make_int4(0,0,0,0);
        if (hasNext) {
            const int* ip = idx + ((t + GRID) * TILE + gp) * NHEADS + gh;
            ni0 = *reinterpret_cast<const int4*>(ip);
            ni1 = *reinterpret_cast<const int4*>(ip + 4);
        }

        unsigned long long acc[16];

        // ---- layer 1: rows 0..31 -> rows 0..63 (in place) ----
        layer_acc<D_IN>(BUF, W1, bb, j0, p0, acc);
        __syncthreads();
        layer_store(BUF, j0, p0, acc);
        __syncthreads();

        // -- table LDGs for NEXT tile (hidden under layers 2-4) --
        float2 nv[8];
        if (hasNext) {
            const int nii[8] = { ni0.x, ni0.y, ni0.z, ni0.w,
                                 ni1.x, ni1.y, ni1.z, ni1.w };
            #pragma unroll
            for (int i = 0; i < 8; i++)
                nv[i] = *reinterpret_cast<const float2*>(
                    tables + ((long)(gh + i) * M_TBL + nii[i]) * 2);
        }

        // ---- layer 2 (in place) ----
        layer_acc<HID>(BUF, W2, bb + 64, j0, p0, acc);
        __syncthreads();
        layer_store(BUF, j0, p0, acc);
        __syncthreads();

        // ---- layer 3 (in place) ----
        layer_acc<HID>(BUF, W3, bb + 128, j0, p0, acc);
        __syncthreads();
        layer_store(BUF, j0, p0, acc);
        __syncthreads();

        // ---- layer 4: 64 -> 3, 2 threads per point (k halves), shfl combine ----
        {
            const int p  = tid >> 1;
            const int kb = (tid & 1) * 32;
            float o0 = 0.f, o1 = 0.f, o2 = 0.f;
            #pragma unroll 8
            for (int k = kb; k < kb + 32; k++) {
                const float a = BUF[k * STRIDE + p];
                o0 = fmaf(a, W4[k * NOUT + 0], o0);
                o1 = fmaf(a, W4[k * NOUT + 1], o1);
                o2 = fmaf(a, W4[k * NOUT + 2], o2);
            }
            o0 += __shfl_down_sync(0xFFFFFFFFu, o0, 1);
            o1 += __shfl_down_sync(0xFFFFFFFFu, o1, 1);
            o2 += __shfl_down_sync(0xFFFFFFFFu, o2, 1);
            if ((tid & 1) == 0) {
                float* op = out + (pbase + p) * NOUT;
                op[0] = o0 + bb[192];
                op[1] = o1 + bb[193];
                op[2] = o2 + bb[194];
            }
        }
        __syncthreads();

        // ---- park NEXT tile's gather into rows 0..31 ----
        if (hasNext) {
            #pragma unroll
            for (int i = 0; i < 8; i++) {
                BUF[(2 * (gh + i)    ) * STRIDE + gp] = nv[i].x;
                BUF[(2 * (gh + i) + 1) * STRIDE + gp] = nv[i].y;
            }
            __syncthreads();
        }
    }
}

extern "C" void kernel_launch(void* const* d_in, const int* in_sizes, int n_in,
                              void* d_out, int out_size)
{
    static int init = 0;
    if (!init) {
        cudaFuncSetAttribute(ngp_persist3_kernel,
                             cudaFuncAttributeMaxDynamicSharedMemorySize,
                             SMEM_BYTES);
        init = 1;
    }
    ngp_persist3_kernel<<<GRID, THREADS, SMEM_BYTES>>>(
        (const int*)d_in[0], (const float*)d_in[1],
        (const float*)d_in[2], (const float*)d_in[3],
        (const float*)d_in[4], (const float*)d_in[5],
        (const float*)d_in[6], (const float*)d_in[7],
        (const float*)d_in[8], (const float*)d_in[9],
        (float*)d_out);
}

// round 7
// speedup vs baseline: 1.0725x; 1.0633x over previous
#include <cuda_runtime.h>
#include <cstdint>

#define NHEADS   16
#define M_TBL    524288
#define D_IN     32
#define HID      64
#define NOUT     3
#define TILE     128
#define THREADS  256
#define NTILES   16384
#define GRID     444            // persistent: 3 CTAs per SM
#define STRIDE   132            // padded row stride (floats)

// Weights in constant memory. j-block is per-WARP, so every weight access is
// warp-uniform -> LDCU through the uniform-const port: zero L1 crossbar use.
__constant__ float cW1[D_IN * HID];   // [k][j] row-major
__constant__ float cW2[HID * HID];
__constant__ float cW3[HID * HID];
__constant__ float cW4[HID * NOUT];
__constant__ float cb1[HID];
__constant__ float cb2[HID];
__constant__ float cb3[HID];
__constant__ float cb4[NOUT];

// activation buffer only: 64 rows x STRIDE
#define SMEM_FLOATS (HID * STRIDE)
#define SMEM_BYTES  (SMEM_FLOATS * 4)        // 33792 B -> 3 CTAs/SM easily

#define FMA2(acc, a, w) \
    asm("fma.rn.f32x2 %0, %1, %2, %0;" : "+l"(acc) : "l"(a), "l"(w))
#define PACK2(d, s) \
    asm("mov.b64 %0, {%1, %1};" : "=l"(d) : "f"(s))
#define UNPACK2(lo, hi, s) \
    asm("mov.b64 {%0, %1}, %2;" : "=f"(lo), "=f"(hi) : "l"(s))

// One layer: A[K][STRIDE] x cW[K][64] -> this warp's 8-j block for the lane's
// 4 points. A-side: one contiguous LDS.128 per k (native f32x2 pairs).
// W-side: warp-uniform constant loads (LDCU), packed to pairs on alu pipe.
template<int K>
__device__ __forceinline__ void layer_acc(const float* __restrict__ A,
                                          const float* __restrict__ W,   // const mem
                                          const float* __restrict__ bias,// const mem
                                          int jw, int lane4,
                                          unsigned long long acc[16])
{
    #pragma unroll
    for (int jj = 0; jj < 8; jj++) {
        unsigned long long b;
        PACK2(b, bias[jw + jj]);
        acc[jj * 2 + 0] = b;
        acc[jj * 2 + 1] = b;
    }
    #pragma unroll 4
    for (int k = 0; k < K; k++) {
        const ulonglong2 a =
            *reinterpret_cast<const ulonglong2*>(&A[k * STRIDE + lane4]);
        #pragma unroll
        for (int jj = 0; jj < 8; jj++) {
            unsigned long long wd;
            PACK2(wd, W[k * HID + jw + jj]);      // warp-uniform -> LDCU
            FMA2(acc[jj * 2 + 0], a.x, wd);
            FMA2(acc[jj * 2 + 1], a.y, wd);
        }
    }
}

// relu + store this warp's 8 rows (each row: 32 lanes x 16B contiguous = clean)
__device__ __forceinline__ void layer_store(float* __restrict__ Bout,
                                            int jw, int lane4,
                                            const unsigned long long acc[16])
{
    #pragma unroll
    for (int jj = 0; jj < 8; jj++) {
        float v0, v1, v2, v3;
        UNPACK2(v0, v1, acc[jj * 2 + 0]);
        UNPACK2(v2, v3, acc[jj * 2 + 1]);
        *reinterpret_cast<float4*>(&Bout[(jw + jj) * STRIDE + lane4]) =
            make_float4(fmaxf(v0, 0.f), fmaxf(v1, 0.f),
                        fmaxf(v2, 0.f), fmaxf(v3, 0.f));
    }
}

__global__ __launch_bounds__(THREADS, 3)
void ngp_uniform_kernel(const int* __restrict__ idx,
                        const float* __restrict__ tables,
                        float* __restrict__ out)
{
    extern __shared__ float BUF[];   // [64][STRIDE]; rows 0..31 double as A

    const int tid  = threadIdx.x;
    const int wid  = tid >> 5;
    const int lane = tid & 31;
    const int jw    = wid * 8;       // this warp's j-block
    const int lane4 = lane * 4;      // this lane's 4 consecutive points
    const int gp = tid >> 1;         // gather: point (2 threads/point)
    const int gh = (tid & 1) * 8;    // gather: head start

    // ---- gather first tile into rows 0..31 ----
    {
        const int* ip = idx + ((long)blockIdx.x * TILE + gp) * NHEADS + gh;
        const int4 i0 = *reinterpret_cast<const int4*>(ip);
        const int4 i1 = *reinterpret_cast<const int4*>(ip + 4);
        const int ii[8] = { i0.x, i0.y, i0.z, i0.w, i1.x, i1.y, i1.z, i1.w };
        #pragma unroll
        for (int i = 0; i < 8; i++) {
            const float2 v = *reinterpret_cast<const float2*>(
                tables + ((long)(gh + i) * M_TBL + ii[i]) * 2);
            BUF[(2 * (gh + i)    ) * STRIDE + gp] = v.x;
            BUF[(2 * (gh + i) + 1) * STRIDE + gp] = v.y;
        }
    }
    __syncthreads();

    for (long t = blockIdx.x; t < NTILES; t += GRID) {
        const long pbase = (long)t * TILE;
        const bool hasNext = (t + GRID) < NTILES;

        // -- idx LDG for NEXT tile (latency hidden under layer 1) --
        int4 ni0 = make_int4(0,0,0,0), ni1 = make_int4(0,0,0,0);
        if (hasNext) {
            const int* ip = idx + ((t + GRID) * TILE + gp) * NHEADS + gh;
            ni0 = *reinterpret_cast<const int4*>(ip);
            ni1 = *reinterpret_cast<const int4*>(ip + 4);
        }

        unsigned long long acc[16];

        // ---- layer 1: rows 0..31 -> rows 0..63 (in place) ----
        layer_acc<D_IN>(BUF, cW1, cb1, jw, lane4, acc);
        __syncthreads();
        layer_store(BUF, jw, lane4, acc);
        __syncthreads();

        // -- table LDGs for NEXT tile (hidden under layers 2-4) --
        float2 nv[8];
        if (hasNext) {
            const int nii[8] = { ni0.x, ni0.y, ni0.z, ni0.w,
                                 ni1.x, ni1.y, ni1.z, ni1.w };
            #pragma unroll
            for (int i = 0; i < 8; i++)
                nv[i] = *reinterpret_cast<const float2*>(
                    tables + ((long)(gh + i) * M_TBL + nii[i]) * 2);
        }

        // ---- layer 2 (in place) ----
        layer_acc<HID>(BUF, cW2, cb2, jw, lane4, acc);
        __syncthreads();
        layer_store(BUF, jw, lane4, acc);
        __syncthreads();

        // ---- layer 3 (in place) ----
        layer_acc<HID>(BUF, cW3, cb3, jw, lane4, acc);
        __syncthreads();
        layer_store(BUF, jw, lane4, acc);
        __syncthreads();

        // ---- layer 4: 64 -> 3, 2 threads per point (k halves) + shfl ----
        {
            const int p  = tid >> 1;
            const int kb = (tid & 1) * 32;
            float o0 = 0.f, o1 = 0.f, o2 = 0.f;
            #pragma unroll 8
            for (int k = kb; k < kb + 32; k++) {
                const float a = BUF[k * STRIDE + p];
                o0 = fmaf(a, cW4[k * NOUT + 0], o0);
                o1 = fmaf(a, cW4[k * NOUT + 1], o1);
                o2 = fmaf(a, cW4[k * NOUT + 2], o2);
            }
            o0 += __shfl_down_sync(0xFFFFFFFFu, o0, 1);
            o1 += __shfl_down_sync(0xFFFFFFFFu, o1, 1);
            o2 += __shfl_down_sync(0xFFFFFFFFu, o2, 1);
            if ((tid & 1) == 0) {
                float* op = out + (pbase + p) * NOUT;
                op[0] = o0 + cb4[0];
                op[1] = o1 + cb4[1];
                op[2] = o2 + cb4[2];
            }
        }
        __syncthreads();

        // ---- park NEXT tile's gather into rows 0..31 ----
        if (hasNext) {
            #pragma unroll
            for (int i = 0; i < 8; i++) {
                BUF[(2 * (gh + i)    ) * STRIDE + gp] = nv[i].x;
                BUF[(2 * (gh + i) + 1) * STRIDE + gp] = nv[i].y;
            }
            __syncthreads();
        }
    }
}

extern "C" void kernel_launch(void* const* d_in, const int* in_sizes, int n_in,
                              void* d_out, int out_size)
{
    static int init = 0;
    if (!init) {
        cudaFuncSetAttribute(ngp_uniform_kernel,
                             cudaFuncAttributeMaxDynamicSharedMemorySize,
                             SMEM_BYTES);
        init = 1;
    }

    // stage weights into constant memory (async D2D: graph-capturable)
    cudaMemcpyToSymbolAsync(cW1, d_in[2], D_IN*HID*sizeof(float), 0,
                            cudaMemcpyDeviceToDevice, 0);
    cudaMemcpyToSymbolAsync(cb1, d_in[3], HID*sizeof(float), 0,
                            cudaMemcpyDeviceToDevice, 0);
    cudaMemcpyToSymbolAsync(cW2, d_in[4], HID*HID*sizeof(float), 0,
                            cudaMemcpyDeviceToDevice, 0);
    cudaMemcpyToSymbolAsync(cb2, d_in[5], HID*sizeof(float), 0,
                            cudaMemcpyDeviceToDevice, 0);
    cudaMemcpyToSymbolAsync(cW3, d_in[6], HID*HID*sizeof(float), 0,
                            cudaMemcpyDeviceToDevice, 0);
    cudaMemcpyToSymbolAsync(cb3, d_in[7], HID*sizeof(float), 0,
                            cudaMemcpyDeviceToDevice, 0);
    cudaMemcpyToSymbolAsync(cW4, d_in[8], HID*NOUT*sizeof(float), 0,
                            cudaMemcpyDeviceToDevice, 0);
    cudaMemcpyToSymbolAsync(cb4, d_in[9], NOUT*sizeof(float), 0,
                            cudaMemcpyDeviceToDevice, 0);

    ngp_uniform_kernel<<<GRID, THREADS, SMEM_BYTES>>>(
        (const int*)d_in[0], (const float*)d_in[1], (float*)d_out);
}